// round 2
// baseline (speedup 1.0000x reference)
#include <cuda_runtime.h>

#define NP 8192
#define DE 64

__device__ float g_xt[NP * DE];
__device__ float g_sq[NP];

struct KSmem {
    float As[64 * 64];
    float Bs[64 * 64];
    unsigned long long ckey[4096];
    unsigned long long top[64][16];
    float clg[4096];
    float tlg[64][16];
    float sqi[64];
    float sqj[64];
    float thr[64];
    int   cnt[64];
    int   ncand;
};

__device__ __forceinline__ unsigned fenc(float f) {
    unsigned u = __float_as_uint(f);
    return (u & 0x80000000u) ? ~u : (u | 0x80000000u);
}
__device__ __forceinline__ float fdec(unsigned k) {
    return (k & 0x80000000u) ? __uint_as_float(k ^ 0x80000000u)
                             : __uint_as_float(~k);
}

__global__ void __launch_bounds__(256, 1) k_embed(
        const float* __restrict__ X, const float* __restrict__ W,
        const float* __restrict__ b, float* __restrict__ out) {
    int tid = threadIdx.x;
    int row = (blockIdx.x << 2) + (tid >> 6);
    int col = tid & 63;
    const float* xr = X + (size_t)row * 128;
    float acc = 0.f;
    #pragma unroll 16
    for (int k = 0; k < 128; ++k)
        acc = fmaf(__ldg(xr + k), __ldg(W + k * 64 + col), acc);
    acc = __fadd_rn(acc, __ldg(b + col));
    g_xt[row * 64 + col] = acc;
    out[row * 64 + col] = acc;
}

__global__ void __launch_bounds__(256, 1) k_sq() {
    int lane = threadIdx.x & 31;
    int row = blockIdx.x * 8 + (threadIdx.x >> 5);
    float a = g_xt[row * 64 + lane];
    float c = g_xt[row * 64 + 32 + lane];
    float v = a * a + c * c;
    #pragma unroll
    for (int o = 16; o; o >>= 1) v += __shfl_xor_sync(0xffffffffu, v, o);
    if (!lane) g_sq[row] = v;
}

__global__ void __launch_bounds__(256, 1) k_knn(
        const float* __restrict__ q, const float* __restrict__ tparam,
        float* __restrict__ out) {
    extern __shared__ char smraw[];
    KSmem& sm = *reinterpret_cast<KSmem*>(smraw);
    const int tid = threadIdx.x;
    const int ibase = blockIdx.x * 64;
    const int ti = tid >> 4, tj = tid & 15;
    const float scale = expf(fminf(fmaxf(tparam[0], -5.f), 5.f));
    const float INFF = __int_as_float(0x7f800000);

    if (tid < 64) {
        sm.thr[tid] = INFF;
        sm.cnt[tid] = 0;
        sm.sqi[tid] = g_sq[ibase + tid];
    }
    // Load A tile (64 rows x 64 dims), XOR-swizzled for conflict-free frag reads
    {
        float4* As4 = (float4*)sm.As;
        #pragma unroll
        for (int qd = 0; qd < 4; ++qd) {
            int f4 = qd * 256 + tid;     // float4 index within 64x64 tile
            int r  = f4 >> 4;            // 16 float4 per row
            int kq = f4 & 15;
            float4 v = *(const float4*)&g_xt[(size_t)(ibase + r) * 64 + kq * 4];
            As4[r * 16 + (kq ^ ((r >> 2) & 7))] = v;
        }
    }
    __syncthreads();

    float4* Bs4 = (float4*)sm.Bs;
    const float4* cAs4 = (const float4*)sm.As;
    const float4* cBs4 = (const float4*)sm.Bs;
    const int ca = ti & 7, cb = tj & 7;

    for (int jbase = 0; jbase < NP; jbase += 64) {
        if (tid == 0) sm.ncand = 0;
        if (tid < 64) sm.sqj[tid] = g_sq[jbase + tid];
        #pragma unroll
        for (int qd = 0; qd < 4; ++qd) {
            int f4 = qd * 256 + tid;
            int r  = f4 >> 4;
            int kq = f4 & 15;
            float4 v = *(const float4*)&g_xt[(size_t)(jbase + r) * 64 + kq * 4];
            Bs4[r * 16 + (kq ^ ((r >> 2) & 7))] = v;
        }
        __syncthreads();

        float acc[4][4];
        #pragma unroll
        for (int u = 0; u < 4; u++)
            #pragma unroll
            for (int v = 0; v < 4; v++) acc[u][v] = 0.f;

        #pragma unroll 4
        for (int kq = 0; kq < 16; ++kq) {
            float4 af[4], bf[4];
            #pragma unroll
            for (int u = 0; u < 4; u++) af[u] = cAs4[(ti * 4 + u) * 16 + (kq ^ ca)];
            #pragma unroll
            for (int v = 0; v < 4; v++) bf[v] = cBs4[(tj * 4 + v) * 16 + (kq ^ cb)];
            #pragma unroll
            for (int u = 0; u < 4; u++)
                #pragma unroll
                for (int v = 0; v < 4; v++) {
                    float a0 = acc[u][v];
                    a0 = fmaf(af[u].x, bf[v].x, a0);
                    a0 = fmaf(af[u].y, bf[v].y, a0);
                    a0 = fmaf(af[u].z, bf[v].z, a0);
                    a0 = fmaf(af[u].w, bf[v].w, a0);
                    acc[u][v] = a0;
                }
        }

        // Epilogue: bounded-gumbel prefilter, rare slow path appends candidates
        float sqiu[4], sqjv[4];
        #pragma unroll
        for (int u = 0; u < 4; u++) sqiu[u] = sm.sqi[ti * 4 + u];
        #pragma unroll
        for (int v = 0; v < 4; v++) sqjv[v] = sm.sqj[tj * 4 + v];
        #pragma unroll
        for (int u = 0; u < 4; u++) {
            int r = ti * 4 + u;
            float th = sm.thr[r];
            #pragma unroll
            for (int v = 0; v < 4; v++) {
                float d = __fadd_rn(__fadd_rn(sqiu[u], sqjv[v]),
                                    -__fmul_rn(2.0f, acc[u][v]));
                d = fmaxf(d, 0.0f);
                float lgt = __fmul_rn(d, scale);
                if (lgt - 17.0f <= th) {   // gumbel in [-2.91, 16.64] -> exact bound
                    int j = jbase + tj * 4 + v;
                    float qv = __ldg(&q[(size_t)(ibase + r) * NP + j]);
                    float pert = __fadd_rn(lgt, logf(-logf(qv)));
                    if (pert <= th) {
                        int idx = atomicAdd(&sm.ncand, 1);
                        sm.ckey[idx] = ((unsigned long long)fenc(pert) << 32)
                                     | ((unsigned)r << 16) | (unsigned)j;
                        sm.clg[idx] = lgt;
                    }
                }
            }
        }
        __syncthreads();

        // Owner threads: exact sorted top-16 per row (key asc = perturbed asc, tie: j asc)
        if (tid < 64) {
            int r = tid;
            int cnt = sm.cnt[r];
            int nc = sm.ncand;
            for (int c = 0; c < nc; ++c) {
                unsigned long long k64 = sm.ckey[c];
                if ((((unsigned)k64) >> 16) != (unsigned)r) continue;
                if (cnt >= 16 && k64 >= sm.top[r][15]) continue;
                float lg = sm.clg[c];
                int p = (cnt < 16) ? cnt : 15;
                while (p > 0 && sm.top[r][p - 1] > k64) {
                    sm.top[r][p] = sm.top[r][p - 1];
                    sm.tlg[r][p] = sm.tlg[r][p - 1];
                    --p;
                }
                sm.top[r][p] = k64;
                sm.tlg[r][p] = lg;
                if (cnt < 16) ++cnt;
                if (cnt == 16) sm.thr[r] = fdec((unsigned)(sm.top[r][15] >> 32));
            }
            sm.cnt[r] = cnt;
        }
        __syncthreads();
    }

    // Final outputs: edge_index (as float) + logprobs
    if (tid < 64) {
        int i = ibase + tid;
        #pragma unroll
        for (int s = 0; s < 16; ++s) {
            unsigned long long k64 = sm.top[tid][s];
            int j = (int)(k64 & 0xFFFFu);
            out[524288 + i * 16 + s] = (float)j;   // edge_index[0]
            out[655360 + i * 16 + s] = (float)i;   // edge_index[1]
            out[786432 + i * 16 + s] = -sm.tlg[tid][s];  // logprobs
        }
    }
}

extern "C" void kernel_launch(void* const* d_in, const int* in_sizes, int n_in,
                              void* d_out, int out_size) {
    const float* X = (const float*)d_in[0];
    const float* W = (const float*)d_in[1];
    const float* b = (const float*)d_in[2];
    const float* t = (const float*)d_in[3];
    const float* q = (const float*)d_in[4];
    float* out = (float*)d_out;

    k_embed<<<2048, 256>>>(X, W, b, out);
    k_sq<<<1024, 256>>>();
    int smem = (int)sizeof(KSmem);
    cudaFuncSetAttribute(k_knn, cudaFuncAttributeMaxDynamicSharedMemorySize, smem);
    k_knn<<<128, 256, smem>>>(q, t, out);
}

// round 3
// speedup vs baseline: 1.4921x; 1.4921x over previous
#include <cuda_runtime.h>
#include <math.h>

#define NP 8192

__device__ float g_xt[NP * 64];
__device__ float g_sq[NP];

// ---------------- smem layout for k_knn ----------------
// As / Bs: transposed [kq][row] in float4 units, row-stride 65 float4 (pad kills
// the 8-way STS bank-group conflict of the transpose; GEMM b-frag reads are
// 16 consecutive float4 -> conflict-free; a-frag is 16-lane broadcast).
struct KSmem {
    float As[16 * 65 * 4];            // 16.6 KB
    float Bs[2][16 * 65 * 4];         // 2 x 16.6 KB (double buffer)
    float Cs[64 * 68];                // staged logits, stride 68 -> reader conflict-free
    float sqi[64];
    float sqj[2][64];
    unsigned long long stop[256][16]; // per-thread sorted top-16 keys (ascending)
    float slg[256][16];               // matching logits
};

__device__ __forceinline__ unsigned fenc(float f) {
    unsigned u = __float_as_uint(f);
    return (u & 0x80000000u) ? ~u : (u | 0x80000000u);
}
__device__ __forceinline__ float fdec(unsigned k) {
    return (k & 0x80000000u) ? __uint_as_float(k ^ 0x80000000u)
                             : __uint_as_float(~k);
}

__global__ void __launch_bounds__(256, 1) k_embed(
        const float* __restrict__ X, const float* __restrict__ W,
        const float* __restrict__ b, float* __restrict__ out) {
    int tid = threadIdx.x;
    int row = (blockIdx.x << 2) + (tid >> 6);
    int col = tid & 63;
    const float* xr = X + (size_t)row * 128;
    float acc = 0.f;
    #pragma unroll 16
    for (int k = 0; k < 128; ++k)
        acc = fmaf(__ldg(xr + k), __ldg(W + k * 64 + col), acc);
    acc = __fadd_rn(acc, __ldg(b + col));
    g_xt[row * 64 + col] = acc;
    out[row * 64 + col] = acc;
}

__global__ void __launch_bounds__(256, 1) k_sq() {
    int lane = threadIdx.x & 31;
    int row = blockIdx.x * 8 + (threadIdx.x >> 5);
    float a = g_xt[row * 64 + lane];
    float c = g_xt[row * 64 + 32 + lane];
    float v = a * a + c * c;
    #pragma unroll
    for (int o = 16; o; o >>= 1) v += __shfl_xor_sync(0xffffffffu, v, o);
    if (!lane) g_sq[row] = v;
}

__global__ void __launch_bounds__(256, 1) k_knn(
        const float* __restrict__ q, const float* __restrict__ tparam,
        float* __restrict__ out) {
    extern __shared__ char smraw[];
    KSmem& sm = *reinterpret_cast<KSmem*>(smraw);
    const int tid = threadIdx.x;
    const int ibase = blockIdx.x * 64;
    const int ti = tid >> 4, tj = tid & 15;
    const float scale = expf(fminf(fmaxf(tparam[0], -5.f), 5.f));
    const float INFF = __int_as_float(0x7f800000);

    float4* As4 = (float4*)sm.As;

    // Stage A tile: coalesced row-major LDG, transposed STS into [kq][row].
    #pragma unroll
    for (int qd = 0; qd < 4; ++qd) {
        int f4 = qd * 256 + tid;
        int r  = f4 >> 4;          // row 0..63
        int kq = f4 & 15;          // k-quad 0..15
        float4 v = *(const float4*)&g_xt[(size_t)(ibase + r) * 64 + kq * 4];
        As4[kq * 65 + r] = v;
    }
    if (tid < 64) sm.sqi[tid] = g_sq[ibase + tid];

    // Stage B chunk 0.
    {
        float4* B4 = (float4*)sm.Bs[0];
        #pragma unroll
        for (int qd = 0; qd < 4; ++qd) {
            int f4 = qd * 256 + tid;
            int r  = f4 >> 4;
            int kq = f4 & 15;
            B4[kq * 65 + r] = *(const float4*)&g_xt[(size_t)r * 64 + kq * 4];
        }
        if (tid < 64) sm.sqj[0][tid] = g_sq[tid];
    }
    __syncthreads();

    float sqiu[4];
    #pragma unroll
    for (int u = 0; u < 4; ++u) sqiu[u] = sm.sqi[ti * 4 + u];

    // Selection identity: thread owns (row selr, j === selp mod 4).
    const int selr = tid >> 2, selp = tid & 3;
    float th = INFF;
    int cnt = 0;
    const float* qrow = q + (size_t)(ibase + selr) * NP;
    unsigned long long* mylist = sm.stop[tid];
    float* mylg = sm.slg[tid];

    for (int chunk = 0; chunk < 128; ++chunk) {
        const int cur = chunk & 1, nxt = cur ^ 1;
        const int jbase = chunk * 64;
        const int jn = jbase + 64;

        // Prefetch next B chunk into registers (covers L2/DRAM latency).
        float4 breg0, breg1, breg2, breg3;
        float sqreg = 0.f;
        if (jn < NP) {
            int r0 = tid >> 4, kq0 = tid & 15;
            breg0 = *(const float4*)&g_xt[(size_t)(jn + r0)      * 64 + kq0 * 4];
            breg1 = *(const float4*)&g_xt[(size_t)(jn + r0 + 16) * 64 + kq0 * 4];
            breg2 = *(const float4*)&g_xt[(size_t)(jn + r0 + 32) * 64 + kq0 * 4];
            breg3 = *(const float4*)&g_xt[(size_t)(jn + r0 + 48) * 64 + kq0 * 4];
            if (tid < 64) sqreg = g_sq[jn + tid];
        }

        // ---- GEMM: 64x64 tile, 4x4 frags, same accumulation order as reference ----
        float acc[4][4];
        #pragma unroll
        for (int u = 0; u < 4; ++u)
            #pragma unroll
            for (int v = 0; v < 4; ++v) acc[u][v] = 0.f;

        const float4* B4 = (const float4*)sm.Bs[cur];
        #pragma unroll 4
        for (int kq = 0; kq < 16; ++kq) {
            float4 af[4], bf[4];
            #pragma unroll
            for (int u = 0; u < 4; ++u) af[u] = As4[kq * 65 + ti * 4 + u];
            #pragma unroll
            for (int v = 0; v < 4; ++v) bf[v] = B4[kq * 65 + tj * 4 + v];
            #pragma unroll
            for (int u = 0; u < 4; ++u)
                #pragma unroll
                for (int v = 0; v < 4; ++v) {
                    float a0 = acc[u][v];
                    a0 = fmaf(af[u].x, bf[v].x, a0);
                    a0 = fmaf(af[u].y, bf[v].y, a0);
                    a0 = fmaf(af[u].z, bf[v].z, a0);
                    a0 = fmaf(af[u].w, bf[v].w, a0);
                    acc[u][v] = a0;
                }
        }

        // ---- epilogue: compute logits, stage to Cs ----
        {
            float sqjv[4];
            #pragma unroll
            for (int v = 0; v < 4; ++v) sqjv[v] = sm.sqj[cur][tj * 4 + v];
            #pragma unroll
            for (int u = 0; u < 4; ++u) {
                float lg[4];
                #pragma unroll
                for (int v = 0; v < 4; ++v) {
                    float d = __fadd_rn(__fadd_rn(sqiu[u], sqjv[v]),
                                        -__fmul_rn(2.0f, acc[u][v]));
                    lg[v] = __fmul_rn(fmaxf(d, 0.0f), scale);
                }
                float4 cv = make_float4(lg[0], lg[1], lg[2], lg[3]);
                *(float4*)&sm.Cs[(ti * 4 + u) * 68 + tj * 4] = cv;
            }
        }
        __syncthreads();

        // ---- selection: each thread scans 16 logits of its (row, parity) slice ----
        #pragma unroll 4
        for (int m = 0; m < 16; ++m) {
            int jl = selp + 4 * m;
            float lgt = sm.Cs[selr * 68 + jl];
            // gumbel = -log(-log q) in [-2.92, 16.83]  ->  perturbed >= lgt - 17
            if (lgt - 17.0f <= th) {
                int j = jbase + jl;
                float qv = __ldg(qrow + j);
                float pert = __fadd_rn(lgt, logf(-logf(qv)));
                unsigned long long key =
                    ((unsigned long long)fenc(pert) << 32) | (unsigned)j;
                if (cnt < 16) {
                    int p2 = cnt;
                    while (p2 > 0 && mylist[p2 - 1] > key) {
                        mylist[p2] = mylist[p2 - 1];
                        mylg[p2] = mylg[p2 - 1];
                        --p2;
                    }
                    mylist[p2] = key; mylg[p2] = lgt;
                    if (++cnt == 16) th = fdec((unsigned)(mylist[15] >> 32));
                } else if (key < mylist[15]) {
                    int p2 = 15;
                    while (p2 > 0 && mylist[p2 - 1] > key) {
                        mylist[p2] = mylist[p2 - 1];
                        mylg[p2] = mylg[p2 - 1];
                        --p2;
                    }
                    mylist[p2] = key; mylg[p2] = lgt;
                    th = fdec((unsigned)(mylist[15] >> 32));
                }
            }
        }

        // ---- store prefetched B into next buffer ----
        if (jn < NP) {
            float4* Bn = (float4*)sm.Bs[nxt];
            int r0 = tid >> 4, kq0 = tid & 15;
            Bn[kq0 * 65 + r0]      = breg0;
            Bn[kq0 * 65 + r0 + 16] = breg1;
            Bn[kq0 * 65 + r0 + 32] = breg2;
            Bn[kq0 * 65 + r0 + 48] = breg3;
            if (tid < 64) sm.sqj[nxt][tid] = sqreg;
        }
        __syncthreads();
    }

    // ---- final 4-way merge per row (exact global top-16) ----
    if (tid < 64) {
        int r = tid;
        int i = ibase + r;
        int hd0 = 0, hd1 = 0, hd2 = 0, hd3 = 0;
        const unsigned long long SENT = 0xFFFFFFFFFFFFFFFFull;
        #pragma unroll
        for (int s = 0; s < 16; ++s) {
            unsigned long long k0 = (hd0 < 16) ? sm.stop[r * 4 + 0][hd0] : SENT;
            unsigned long long k1 = (hd1 < 16) ? sm.stop[r * 4 + 1][hd1] : SENT;
            unsigned long long k2 = (hd2 < 16) ? sm.stop[r * 4 + 2][hd2] : SENT;
            unsigned long long k3 = (hd3 < 16) ? sm.stop[r * 4 + 3][hd3] : SENT;
            unsigned long long kb = min(min(k0, k1), min(k2, k3));
            float lg;
            if (kb == k0)      { lg = sm.slg[r * 4 + 0][hd0]; ++hd0; }
            else if (kb == k1) { lg = sm.slg[r * 4 + 1][hd1]; ++hd1; }
            else if (kb == k2) { lg = sm.slg[r * 4 + 2][hd2]; ++hd2; }
            else               { lg = sm.slg[r * 4 + 3][hd3]; ++hd3; }
            int j = (int)(kb & 0xFFFFu);
            out[524288 + i * 16 + s] = (float)j;   // edge_index[0] = neighbor
            out[655360 + i * 16 + s] = (float)i;   // edge_index[1] = row
            out[786432 + i * 16 + s] = -lg;        // logprobs
        }
    }
}

extern "C" void kernel_launch(void* const* d_in, const int* in_sizes, int n_in,
                              void* d_out, int out_size) {
    const float* X = (const float*)d_in[0];
    const float* W = (const float*)d_in[1];
    const float* b = (const float*)d_in[2];
    const float* t = (const float*)d_in[3];
    const float* q = (const float*)d_in[4];
    float* out = (float*)d_out;

    k_embed<<<2048, 256>>>(X, W, b, out);
    k_sq<<<1024, 256>>>();
    int smem = (int)sizeof(KSmem);
    cudaFuncSetAttribute(k_knn, cudaFuncAttributeMaxDynamicSharedMemorySize, smem);
    k_knn<<<128, 256, smem>>>(q, t, out);
}

// round 5
// speedup vs baseline: 2.0580x; 1.3792x over previous
#include <cuda_runtime.h>
#include <math.h>

#define NP 8192

__device__ float g_xt[NP * 64];
__device__ float g_sq[NP];

// Bank math (word index mod 32, per 8-lane phase):
//  As [kq][row]               stride 65 f4 : a-frag broadcast; STS 4kq distinct
//  Bs [kq][(c)*16 + tj]       stride 129 f4: b-frag word=4kq+4tj distinct;
//                                            cp.async writer word=4kq distinct
//  Cs [u*833+ti*52+tj*3+v4]               : STS.128 12tj+4v4 distinct;
//                                            reader 4u+16ti+selp all-32 distinct
struct KSmem {
    float4 As[16 * 65];                // 16.6 KB
    float4 Bs[2][16 * 129];            // 66.0 KB
    float4 Cs[3332];                   // 53.3 KB
    float  sqi[64];
    float  sqj[2][128];
    unsigned long long stop[16][256];  // 32 KB  [slot][tid]
    float  slg[16][256];               // 16 KB
};

__device__ __forceinline__ unsigned fenc(float f) {
    unsigned u = __float_as_uint(f);
    return (u & 0x80000000u) ? ~u : (u | 0x80000000u);
}
__device__ __forceinline__ float fdec(unsigned k) {
    return (k & 0x80000000u) ? __uint_as_float(k ^ 0x80000000u)
                             : __uint_as_float(~k);
}
__device__ __forceinline__ unsigned smaddr(const void* p) {
    unsigned a;
    asm("{ .reg .u64 t; cvta.to.shared.u64 t, %1; cvt.u32.u64 %0, t; }"
        : "=r"(a) : "l"(p));
    return a;
}
__device__ __forceinline__ void cpa16(unsigned dst, const void* src) {
    asm volatile("cp.async.ca.shared.global [%0], [%1], 16;" :: "r"(dst), "l"(src));
}
__device__ __forceinline__ void cpa4(unsigned dst, const void* src) {
    asm volatile("cp.async.ca.shared.global [%0], [%1], 4;" :: "r"(dst), "l"(src));
}
__device__ __forceinline__ void cpcommit() { asm volatile("cp.async.commit_group;"); }
__device__ __forceinline__ void cpwait0()  { asm volatile("cp.async.wait_group 0;" ::: "memory"); }

__global__ void __launch_bounds__(256, 1) k_embed(
        const float* __restrict__ X, const float* __restrict__ W,
        const float* __restrict__ b, float* __restrict__ out) {
    __shared__ float s_acc[256];
    int tid = threadIdx.x;
    int row = (blockIdx.x << 2) + (tid >> 6);
    int col = tid & 63;
    const float* xr = X + (size_t)row * 128;
    float acc = 0.f;
    #pragma unroll 16
    for (int k = 0; k < 128; ++k)
        acc = fmaf(__ldg(xr + k), __ldg(W + k * 64 + col), acc);
    acc = __fadd_rn(acc, __ldg(b + col));
    g_xt[row * 64 + col] = acc;
    out[row * 64 + col] = acc;
    s_acc[tid] = acc;
    __syncthreads();
    if (tid < 128) {
        int sub = tid >> 5, lane = tid & 31;
        float a = s_acc[sub * 64 + lane];
        float c = s_acc[sub * 64 + 32 + lane];
        float v = a * a + c * c;
        #pragma unroll
        for (int o = 16; o; o >>= 1) v += __shfl_xor_sync(0xffffffffu, v, o);
        if (!lane) g_sq[(blockIdx.x << 2) + sub] = v;
    }
}

// Stage 128-column chunk: float4 = k-quad (dims kq*4..+3) of column j,
// stored at [kq*129 + (j&7)*16 + (j>>3)].
__device__ __forceinline__ void fill_b(KSmem& sm, int buf, int jb, int tid) {
    #pragma unroll
    for (int it = 0; it < 8; ++it) {
        int f = it * 256 + tid;
        int j = f >> 4, kq = f & 15;
        unsigned dst = smaddr(&sm.Bs[buf][kq * 129 + (j & 7) * 16 + (j >> 3)]);
        cpa16(dst, &g_xt[(size_t)(jb + j) * 64 + kq * 4]);
    }
    if (tid < 128) cpa4(smaddr(&sm.sqj[buf][tid]), &g_sq[jb + tid]);
    cpcommit();
}

__global__ void __launch_bounds__(256, 1) k_knn(
        const float* __restrict__ q, const float* __restrict__ tparam,
        float* __restrict__ out) {
    extern __shared__ char smraw[];
    KSmem& sm = *reinterpret_cast<KSmem*>(smraw);
    const int tid = threadIdx.x;
    const int ibase = blockIdx.x * 64;
    const int ti = tid >> 4, tj = tid & 15;
    const float scale = expf(fminf(fmaxf(tparam[0], -5.f), 5.f));
    const float INFF = __int_as_float(0x7f800000);

    fill_b(sm, 0, 0, tid);
    #pragma unroll
    for (int qd = 0; qd < 4; ++qd) {
        int f = qd * 256 + tid;
        int r = f >> 4, kq = f & 15;
        sm.As[kq * 65 + r] = *(const float4*)&g_xt[(size_t)(ibase + r) * 64 + kq * 4];
    }
    if (tid < 64) sm.sqi[tid] = g_sq[ibase + tid];
    cpwait0();
    __syncthreads();

    float sqiu[4];
    #pragma unroll
    for (int u = 0; u < 4; ++u) sqiu[u] = sm.sqi[ti * 4 + u];

    const int selr = tid >> 2, selp = tid & 3;
    const int su = selr & 3, sti = selr >> 2;
    float th = INFF;
    int cnt = 0;
    const float* qrow = q + (size_t)(ibase + selr) * NP;
    const float* CsF = (const float*)sm.Cs;

    for (int chunk = 0; chunk < 64; ++chunk) {
        const int cur = chunk & 1, nxt = cur ^ 1;
        const int jbase = chunk * 128;
        const int jn = jbase + 128;
        if (jn < NP) fill_b(sm, nxt, jn, tid);

        // ---- GEMM 64x128, 4x8 frags; k-quad float4s, sequential-k fma chain ----
        float acc[4][8];
        #pragma unroll
        for (int u = 0; u < 4; ++u)
            #pragma unroll
            for (int c = 0; c < 8; ++c) acc[u][c] = 0.f;

        const float4* B4 = sm.Bs[cur];
        #pragma unroll 4
        for (int kq = 0; kq < 16; ++kq) {
            float4 af[4];
            #pragma unroll
            for (int u = 0; u < 4; ++u) af[u] = sm.As[kq * 65 + ti * 4 + u];
            #pragma unroll
            for (int c = 0; c < 8; ++c) {
                float4 bf = B4[kq * 129 + c * 16 + tj];
                #pragma unroll
                for (int u = 0; u < 4; ++u) {
                    float a0 = acc[u][c];
                    a0 = fmaf(af[u].x, bf.x, a0);
                    a0 = fmaf(af[u].y, bf.y, a0);
                    a0 = fmaf(af[u].z, bf.z, a0);
                    a0 = fmaf(af[u].w, bf.w, a0);
                    acc[u][c] = a0;
                }
            }
        }

        // ---- epilogue: logits -> Cs ----
        {
            float sqjv[8];
            #pragma unroll
            for (int c = 0; c < 8; ++c) sqjv[c] = sm.sqj[cur][tj * 8 + c];
            #pragma unroll
            for (int u = 0; u < 4; ++u) {
                #pragma unroll
                for (int v4 = 0; v4 < 2; ++v4) {
                    float lg[4];
                    #pragma unroll
                    for (int v = 0; v < 4; ++v) {
                        float d = __fadd_rn(__fadd_rn(sqiu[u], sqjv[v4 * 4 + v]),
                                            -__fmul_rn(2.0f, acc[u][v4 * 4 + v]));
                        lg[v] = __fmul_rn(fmaxf(d, 0.0f), scale);
                    }
                    sm.Cs[u * 833 + ti * 52 + tj * 3 + v4] =
                        make_float4(lg[0], lg[1], lg[2], lg[3]);
                }
            }
        }
        __syncthreads();

        // ---- selection: thread owns (row selr, j===selp mod 4): 32 candidates ----
        #pragma unroll 4
        for (int m = 0; m < 32; ++m) {
            float lgt = CsF[4 * (su * 833 + sti * 52 + (m >> 1) * 3 + (m & 1)) + selp];
            if (lgt - 17.0f <= th) {   // gumbel in [-2.92, 16.7] -> exact bound
                int j = jbase + selp + 4 * m;
                float qv = __ldg(qrow + j);
                float pert = __fadd_rn(lgt, logf(-logf(qv)));
                unsigned long long key =
                    ((unsigned long long)fenc(pert) << 32) | (unsigned)j;
                if (cnt < 16) {
                    int p2 = cnt;
                    while (p2 > 0 && sm.stop[p2 - 1][tid] > key) {
                        sm.stop[p2][tid] = sm.stop[p2 - 1][tid];
                        sm.slg[p2][tid]  = sm.slg[p2 - 1][tid];
                        --p2;
                    }
                    sm.stop[p2][tid] = key; sm.slg[p2][tid] = lgt;
                    if (++cnt == 16) th = fdec((unsigned)(sm.stop[15][tid] >> 32));
                } else if (key < sm.stop[15][tid]) {
                    int p2 = 15;
                    while (p2 > 0 && sm.stop[p2 - 1][tid] > key) {
                        sm.stop[p2][tid] = sm.stop[p2 - 1][tid];
                        sm.slg[p2][tid]  = sm.slg[p2 - 1][tid];
                        --p2;
                    }
                    sm.stop[p2][tid] = key; sm.slg[p2][tid] = lgt;
                    th = fdec((unsigned)(sm.stop[15][tid] >> 32));
                }
            }
        }
        cpwait0();
        __syncthreads();
    }

    // ---- final 4-way merge per row ----
    if (tid < 64) {
        int r = tid, i = ibase + r;
        int hd0 = 0, hd1 = 0, hd2 = 0, hd3 = 0;
        const unsigned long long SENT = 0xFFFFFFFFFFFFFFFFull;
        #pragma unroll
        for (int s = 0; s < 16; ++s) {
            unsigned long long k0 = (hd0 < 16) ? sm.stop[hd0][r * 4 + 0] : SENT;
            unsigned long long k1 = (hd1 < 16) ? sm.stop[hd1][r * 4 + 1] : SENT;
            unsigned long long k2 = (hd2 < 16) ? sm.stop[hd2][r * 4 + 2] : SENT;
            unsigned long long k3 = (hd3 < 16) ? sm.stop[hd3][r * 4 + 3] : SENT;
            unsigned long long kb = min(min(k0, k1), min(k2, k3));
            float lg;
            if (kb == k0)      { lg = sm.slg[hd0][r * 4 + 0]; ++hd0; }
            else if (kb == k1) { lg = sm.slg[hd1][r * 4 + 1]; ++hd1; }
            else if (kb == k2) { lg = sm.slg[hd2][r * 4 + 2]; ++hd2; }
            else               { lg = sm.slg[hd3][r * 4 + 3]; ++hd3; }
            int j = (int)(kb & 0xFFFFu);
            out[524288 + i * 16 + s] = (float)j;
            out[655360 + i * 16 + s] = (float)i;
            out[786432 + i * 16 + s] = -lg;
        }
    }
}

extern "C" void kernel_launch(void* const* d_in, const int* in_sizes, int n_in,
                              void* d_out, int out_size) {
    const float* X = (const float*)d_in[0];
    const float* W = (const float*)d_in[1];
    const float* b = (const float*)d_in[2];
    const float* t = (const float*)d_in[3];
    const float* q = (const float*)d_in[4];
    float* out = (float*)d_out;

    k_embed<<<2048, 256>>>(X, W, b, out);
    int smem = (int)sizeof(KSmem);
    cudaFuncSetAttribute(k_knn, cudaFuncAttributeMaxDynamicSharedMemorySize, smem);
    k_knn<<<128, 256, smem>>>(q, t, out);
}